// round 12
// baseline (speedup 1.0000x reference)
#include <cuda_runtime.h>
#include <cuda_bf16.h>
#include <cstdint>
#include <math.h>

// ---------------- problem constants ----------------
#define NTOK   4096      // B*T
#define TSEQ   512
#define NBATCH 8
#define DIMIN  768
#define WIDTH  8192
#define NHEADS 8
#define NEMBDS 128
#define DHQK   16
#define DHV    1024
#define KVAL   32
#define LAM    (1.0f/3072.0f)   // 1/(4*DIMIN)

#if defined(__CUDA_ARCH_FEAT_SM103_ALL) || defined(__CUDA_ARCH_FEAT_SM100_ALL) || defined(__CUDA_ARCH_SPECIFIC__)
#define TC_OK 1
#else
#define TC_OK 0
#endif

// ---------------- scratch (device globals; no allocation allowed) ----------------
__device__ float g_x   [NTOK*DIMIN];
__device__ float g_x2  [NTOK*DIMIN];
__device__ float g_zin [(size_t)NTOK*WIDTH];   // reused for z_novel
__device__ float g_q   [NTOK*NEMBDS];
__device__ float g_k   [NTOK*NEMBDS];
__device__ float g_v   [(size_t)NTOK*WIDTH];
__device__ float g_vT  [(size_t)NTOK*WIDTH];   // vT (step 6-7); also split-K partials (steps 3, 9)
__device__ float g_att [(size_t)NBATCH*NHEADS*TSEQ*TSEQ];
__device__ float g_o   [(size_t)NTOK*WIDTH];
__device__ float g_zp  [(size_t)NTOK*WIDTH];
__device__ float g_Dz  [NTOK*DIMIN];
__device__ float g_Dt  [DIMIN*WIDTH];          // D^T fp32 (for Dz GEMM)
__device__ float g_proj[NTOK];
__device__ float g_tkv [NTOK*KVAL];
__device__ int   g_tki [NTOK*KVAL];

#define QK_PART  524288          // 4096*128 elems per chunk
#define DZ_PART  3145728         // 4096*768 elems per chunk

// =====================================================================
// tcgen05 split-bf16 GEMM:  C[M,N] = alpha*(A[M,K] @ B[N,K]^T)(+bias)(+relu)
// Tile 256x128, K-stage 64, SW128 swizzle (validated R8/R10 encodings), 2-stage.
// M=256 as two independent 128-row MMA halves -> TMEM cols [0,128),[128,256).
// shiftA: A row r reads source row r-1 (zero when r % TSEQ == 0).
// ldab: row stride of A and B (elements). K may be a chunk of it (split-K).
// =====================================================================
#define GBK 64
#define PLANE_BYTES 16384           // 128 rows x 64 bf16 (128B/row, SW128)
#define STAGE_BYTES (6*PLANE_BYTES)
#define TG_DSMEM (2*STAGE_BYTES + 1024 + 64)

__device__ __forceinline__ uint32_t smem_addr_u32(const void* p) {
    uint32_t a;
    asm("{ .reg .u64 t; cvta.to.shared.u64 t, %1; cvt.u32.u64 %0, t; }" : "=r"(a) : "l"(p));
    return a;
}

#if TC_OK
// SW128 K-major SMEM descriptor (version=1, layout=2, SBO=64, LBO=1)
__device__ __forceinline__ uint64_t mk_desc(uint32_t addr) {
    return ((uint64_t)2 << 61) | ((uint64_t)1 << 46) | ((uint64_t)64 << 32)
         | ((uint64_t)1 << 16) | ((uint64_t)((addr >> 4) & 0x3FFF));
}

__device__ __forceinline__ void mma_f16_ss(uint32_t d, uint64_t a, uint64_t b,
                                           uint32_t idesc, uint32_t en) {
    asm volatile(
        "{\n\t.reg .pred p;\n\tsetp.ne.u32 p, %4, 0;\n\t"
        "tcgen05.mma.cta_group::1.kind::f16 [%0], %1, %2, %3, {%5,%5,%5,%5}, p;\n\t}"
        :: "r"(d), "l"(a), "l"(b), "r"(idesc), "r"(en), "r"(0u) : "memory");
}

#define MBAR_INIT(a, c) \
    asm volatile("mbarrier.init.shared.b64 [%0], %1;" :: "r"(a), "r"(c) : "memory")

#define MBAR_WAIT(mbar, par) do { \
    uint32_t _m = (mbar); uint32_t _p = (par); uint32_t _done; \
    asm volatile("{\n\t.reg .pred p;\n\t" \
        "mbarrier.try_wait.parity.acquire.cta.shared::cta.b64 p, [%1], %2;\n\t" \
        "selp.b32 %0, 1, 0, p;\n\t}" : "=r"(_done) : "r"(_m), "r"(_p) : "memory"); \
    if (!_done) { \
        asm volatile("{\n\t.reg .pred P1;\n\tWL_%=:\n\t" \
            "mbarrier.try_wait.parity.acquire.cta.shared::cta.b64 P1, [%0], %1, 0x989680;\n\t" \
            "@P1 bra.uni WD_%=;\n\tbra.uni WL_%=;\n\tWD_%=:\n\t}" \
            :: "r"(_m), "r"(_p) : "memory"); \
    } \
} while (0)

#define LDTM_X32(r, ta) \
    asm volatile("tcgen05.ld.sync.aligned.32x32b.x32.b32 " \
        "{%0,%1,%2,%3,%4,%5,%6,%7,%8,%9,%10,%11,%12,%13,%14,%15," \
        "%16,%17,%18,%19,%20,%21,%22,%23,%24,%25,%26,%27,%28,%29,%30,%31}, [%32];" \
        : "=r"((r)[0]),"=r"((r)[1]),"=r"((r)[2]),"=r"((r)[3]), \
          "=r"((r)[4]),"=r"((r)[5]),"=r"((r)[6]),"=r"((r)[7]), \
          "=r"((r)[8]),"=r"((r)[9]),"=r"((r)[10]),"=r"((r)[11]), \
          "=r"((r)[12]),"=r"((r)[13]),"=r"((r)[14]),"=r"((r)[15]), \
          "=r"((r)[16]),"=r"((r)[17]),"=r"((r)[18]),"=r"((r)[19]), \
          "=r"((r)[20]),"=r"((r)[21]),"=r"((r)[22]),"=r"((r)[23]), \
          "=r"((r)[24]),"=r"((r)[25]),"=r"((r)[26]),"=r"((r)[27]), \
          "=r"((r)[28]),"=r"((r)[29]),"=r"((r)[30]),"=r"((r)[31]) \
        : "r"(ta))

// load 128 rows x 64 k fp32, split hi/lo bf16, store SW128-swizzled.
__device__ __forceinline__ void ldsplit(const float* __restrict__ G, int ld, int rowbase,
                                        int kcol0, uint32_t sH, uint32_t sL, int shiftTok)
{
    const int tid = threadIdx.x;
    #pragma unroll
    for (int j = 0; j < 8; j++) {
        int idx = j*256 + tid;
        int row = idx >> 4, c4 = idx & 15;
        int gr = rowbase + row;
        float4 v;
        if (shiftTok && ((gr & (TSEQ-1)) == 0)) {
            v.x = 0.f; v.y = 0.f; v.z = 0.f; v.w = 0.f;
        } else {
            v = *(const float4*)(G + (size_t)(gr - shiftTok)*ld + kcol0 + c4*4);
        }
        __nv_bfloat162 h01 = __floats2bfloat162_rn(v.x, v.y);
        __nv_bfloat162 h23 = __floats2bfloat162_rn(v.z, v.w);
        float2 f01 = __bfloat1622float2(h01);
        float2 f23 = __bfloat1622float2(h23);
        __nv_bfloat162 l01 = __floats2bfloat162_rn(v.x - f01.x, v.y - f01.y);
        __nv_bfloat162 l23 = __floats2bfloat162_rn(v.z - f23.x, v.w - f23.y);
        uint32_t off = row*128 + c4*8;
        uint32_t sw  = off ^ ((off >> 3) & 0x70);   // SW128
        unsigned uh01 = *reinterpret_cast<unsigned*>(&h01);
        unsigned uh23 = *reinterpret_cast<unsigned*>(&h23);
        unsigned ul01 = *reinterpret_cast<unsigned*>(&l01);
        unsigned ul23 = *reinterpret_cast<unsigned*>(&l23);
        asm volatile("st.shared.v2.b32 [%0], {%1,%2};" :: "r"(sH + sw), "r"(uh01), "r"(uh23));
        asm volatile("st.shared.v2.b32 [%0], {%1,%2};" :: "r"(sL + sw), "r"(ul01), "r"(ul23));
    }
}
#endif  // TC_OK

template<bool RELU, bool HASB>
__global__ void __launch_bounds__(256, 1) tgemm(
    const float* __restrict__ Ag, const float* __restrict__ Bg,
    float* __restrict__ Cg, const float* __restrict__ bias,
    int K, int ldab, int ldc, int MT, int NT, float alpha, int shiftA,
    long sA, long sB, long sC1, long sC2, int zdiv,
    const float* Ag2, const float* Bg2, float* Cg2, const float* bias2, int shiftA2)
{
    if (blockIdx.y == 1) { Ag = Ag2; Bg = Bg2; Cg = Cg2; bias = bias2; shiftA = shiftA2; }
    if (gridDim.z > 1) {
        int z = blockIdx.z;
        Ag += (long)z * sA;
        Bg += (long)z * sB;
        Cg += (long)(z / zdiv) * sC1 + (long)(z % zdiv) * sC2;
    }

    extern __shared__ char smem[];
    const int tid = threadIdx.x;

    // raster: groups of 8 N-tiles, M-major inside group
    int bid = blockIdx.x;
    const int GW = 8;
    int tpg = MT * GW;
    int g = bid / tpg, r = bid % tpg;
    int n0 = g * GW;
    int gw = NT - n0; if (gw > GW) gw = GW;
    const int bm = (r / gw) * 256;        // 256-row M tile
    const int bn = (n0 + r % gw) * 128;   // 128-col N tile

#if TC_OK
    uint32_t SB   = (smem_addr_u32(smem) + 1023u) & ~1023u;
    uint32_t ctrl = SB + 2*STAGE_BYTES;   // [ctrl]=tmem ptr, [ctrl+16/+24]=mbar[0/1]

    if (tid < 32) {
        asm volatile("tcgen05.alloc.cta_group::1.sync.aligned.shared::cta.b32 [%0], %1;"
                     :: "r"(ctrl), "r"(256u) : "memory");
        asm volatile("tcgen05.relinquish_alloc_permit.cta_group::1.sync.aligned;");
    }
    if (tid == 0) { MBAR_INIT(ctrl+16, 1); MBAR_INIT(ctrl+24, 1); }
    __syncthreads();
    uint32_t tmem;
    asm("ld.shared.b32 %0, [%1];" : "=r"(tmem) : "r"(ctrl));

    const uint32_t idesc = (1u<<4) | (1u<<7) | (1u<<10) | (16u<<17) | (8u<<24); // bf16, f32 acc, N=128, M=128
    const int KT = K / GBK;

    // prologue: tile 0 -> stage 0
    ldsplit(Ag, ldab, bm,       0, SB,                 SB +   PLANE_BYTES, shiftA);
    ldsplit(Ag, ldab, bm + 128, 0, SB + 2*PLANE_BYTES, SB + 3*PLANE_BYTES, shiftA);
    ldsplit(Bg, ldab, bn,       0, SB + 4*PLANE_BYTES, SB + 5*PLANE_BYTES, 0);
    __syncthreads();

    int ph0 = 0, ph1 = 0;
    for (int kt = 0; kt < KT; ++kt) {
        const int s = kt & 1;
        if (tid == 0) {
            asm volatile("fence.proxy.async.shared::cta;" ::: "memory");
            uint32_t base = SB + s*STAGE_BYTES;
            uint64_t dBh = mk_desc(base + 4*PLANE_BYTES);
            uint64_t dBl = mk_desc(base + 5*PLANE_BYTES);
            uint32_t en0 = (kt > 0) ? 1u : 0u;
            #pragma unroll
            for (int half = 0; half < 2; ++half) {
                uint64_t dAh = mk_desc(base + half*2*PLANE_BYTES);
                uint64_t dAl = mk_desc(base + half*2*PLANE_BYTES + PLANE_BYTES);
                uint32_t dcol = tmem + half*128;
                uint32_t eh = en0;
                #pragma unroll
                for (int st = 0; st < 4; ++st) {
                    uint64_t o = 2*st;     // 16 bf16 = 32B = 2 x 16B units
                    mma_f16_ss(dcol, dAh + o, dBh + o, idesc, eh); eh = 1u;
                    mma_f16_ss(dcol, dAh + o, dBl + o, idesc, 1u);
                    mma_f16_ss(dcol, dAl + o, dBh + o, idesc, 1u);
                }
            }
            asm volatile("tcgen05.commit.cta_group::1.mbarrier::arrive::one.shared::cluster.b64 [%0];"
                         :: "r"(ctrl + 16 + 8*s) : "memory");
            if (kt >= 1 && kt + 1 < KT) {      // free the other stage
                int so = s ^ 1;
                if (so) { MBAR_WAIT(ctrl+24, ph1); ph1 ^= 1; }
                else    { MBAR_WAIT(ctrl+16, ph0); ph0 ^= 1; }
            }
        }
        __syncthreads();
        if (kt + 1 < KT) {
            uint32_t base = SB + (s^1)*STAGE_BYTES;
            int k0 = (kt+1)*GBK;
            ldsplit(Ag, ldab, bm,       k0, base,                 base +   PLANE_BYTES, shiftA);
            ldsplit(Ag, ldab, bm + 128, k0, base + 2*PLANE_BYTES, base + 3*PLANE_BYTES, shiftA);
            ldsplit(Bg, ldab, bn,       k0, base + 4*PLANE_BYTES, base + 5*PLANE_BYTES, 0);
        }
        __syncthreads();
    }
    if (tid == 0) {
        int sl = (KT-1) & 1;
        if (sl) { MBAR_WAIT(ctrl+24, ph1); }
        else    { MBAR_WAIT(ctrl+16, ph0); }
    }
    __syncthreads();
    asm volatile("tcgen05.fence::after_thread_sync;" ::: "memory");

    // epilogue: TMEM -> fp32 C ; warps 0-3: M-half 0, warps 4-7: M-half 1
    {
        const int wid = tid >> 5, lane = tid & 31;
        const int half = wid >> 2;
        const int row = bm + half*128 + (wid & 3)*32 + lane;
        #pragma unroll
        for (int cb = 0; cb < 128; cb += 32) {
            uint32_t rr[32];
            LDTM_X32(rr, tmem + half*128 + cb);
            asm volatile("tcgen05.wait::ld.sync.aligned;" ::: "memory");
            float* crow = Cg + (size_t)row*ldc + bn + cb;
            #pragma unroll
            for (int q4 = 0; q4 < 8; q4++) {
                float4 o4;
                float vv[4];
                #pragma unroll
                for (int t = 0; t < 4; t++) {
                    float v = alpha * __uint_as_float(rr[q4*4 + t]);
                    if (HASB) v += bias[bn + cb + q4*4 + t];
                    if (RELU) v = fmaxf(v, 0.f);
                    vv[t] = v;
                }
                o4.x = vv[0]; o4.y = vv[1]; o4.z = vv[2]; o4.w = vv[3];
                *(float4*)(crow + q4*4) = o4;
            }
        }
    }
    __syncthreads();
    if (tid < 32) {
        asm volatile("tcgen05.dealloc.cta_group::1.sync.aligned.b32 %0, %1;"
                     :: "r"(tmem), "r"(256u));
    }
#else
    // naive SIMT fallback — correctness-only body for the non-arch-specific
    // compilation pass; the sm_103a cubin above is what actually runs.
    (void)smem;
    for (int e = tid; e < 256*128; e += 256) {
        int i = e >> 7, j = e & 127;
        int gr = bm + i;
        bool zero = shiftA && ((gr & (TSEQ-1)) == 0);
        const float* arow = Ag + (size_t)(gr - shiftA)*ldab;
        const float* brow = Bg + (size_t)(bn + j)*ldab;
        float acc = 0.f;
        if (!zero)
            for (int k = 0; k < K; k++) acc += arow[k] * brow[k];
        float v = alpha * acc;
        if (HASB) v += bias[bn + j];
        if (RELU) v = fmaxf(v, 0.f);
        Cg[(size_t)gr*ldc + bn + j] = v;
    }
#endif
}

// ---------------- split-K reduce kernels ----------------
__global__ void reduce_qk_kernel(const float* __restrict__ part,
                                 const float* __restrict__ bq, const float* __restrict__ bk)
{
    const int y = blockIdx.y;
    const int i = blockIdx.x * 256 + threadIdx.x;     // < QK_PART
    const float* p = part + (size_t)y * 4 * QK_PART;
    float s = p[i] + p[i + QK_PART] + p[i + 2*QK_PART] + p[i + 3*QK_PART];
    s += (y ? bk : bq)[i & (NEMBDS-1)];
    (y ? g_k : g_q)[i] = s;
}

__global__ void reduce_dz_kernel(const float* __restrict__ part)
{
    const int i = blockIdx.x * 256 + threadIdx.x;     // < NTOK*DIMIN
    g_Dz[i] = part[i] + part[i + DZ_PART];
}

// ---------------- elementwise / glue kernels ----------------
__global__ void sub_b_kernel(const float* __restrict__ xin, const float* __restrict__ b)
{
    int i = blockIdx.x * 256 + threadIdx.x;
    g_x[i] = xin[i] - b[i % DIMIN];
}

__global__ void transpose_kernel(const float* __restrict__ D)  // -> g_Dt [DIMIN, WIDTH]
{
    __shared__ float t[32][33];
    int bx = blockIdx.x * 32;   // over DIMIN
    int by = blockIdx.y * 32;   // over WIDTH
    int x = threadIdx.x, y = threadIdx.y;  // 32 x 8
    #pragma unroll
    for (int i = 0; i < 32; i += 8)
        t[y+i][x] = D[(size_t)(by + y + i) * DIMIN + bx + x];
    __syncthreads();
    #pragma unroll
    for (int i = 0; i < 32; i += 8)
        g_Dt[(size_t)(bx + y + i) * WIDTH + by + x] = t[x][y+i];
}

__global__ void transpose_v_kernel()   // g_v [tok, W] -> g_vT per-batch [W, TSEQ]
{
    __shared__ float t[32][33];
    int bx = blockIdx.x * 32;   // over WIDTH
    int by = blockIdx.y * 32;   // over TSEQ
    int b  = blockIdx.z;
    int x = threadIdx.x, y = threadIdx.y;  // 32 x 8
    #pragma unroll
    for (int i = 0; i < 32; i += 8)
        t[y+i][x] = g_v[(size_t)(b*TSEQ + by + y + i) * WIDTH + bx + x];
    __syncthreads();
    #pragma unroll
    for (int i = 0; i < 32; i += 8)
        g_vT[(size_t)b*WIDTH*TSEQ + (size_t)(bx + y + i) * TSEQ + by + x] = t[x][y+i];
}

__global__ void attn_softmax_kernel()
{
    const int t  = blockIdx.x;
    const int bh = blockIdx.y;
    const int b  = bh >> 3, h = bh & 7;
    __shared__ float qs[DHQK];
    __shared__ float sc[TSEQ];
    __shared__ float red[128];
    const int tid = threadIdx.x;

    if (tid < DHQK) qs[tid] = g_q[(long)(b*TSEQ + t)*NEMBDS + h*DHQK + tid];
    __syncthreads();

    float lmax = -1e30f;
    for (int s = tid; s < TSEQ; s += 128) {
        float val = -1e30f;
        if (s <= t) {
            const float* kp = g_k + (long)(b*TSEQ + s)*NEMBDS + h*DHQK;
            float d = 0.f;
            #pragma unroll
            for (int i = 0; i < DHQK; i++) d += qs[i] * kp[i];
            val = d * 0.25f;
        }
        sc[s] = val;
        lmax = fmaxf(lmax, val);
    }
    red[tid] = lmax; __syncthreads();
    for (int o = 64; o > 0; o >>= 1) { if (tid < o) red[tid] = fmaxf(red[tid], red[tid+o]); __syncthreads(); }
    const float mx = red[0];
    __syncthreads();
    float lsum = 0.f;
    for (int s = tid; s < TSEQ; s += 128) {
        float e = (s <= t) ? expf(sc[s] - mx) : 0.f;
        sc[s] = e; lsum += e;
    }
    red[tid] = lsum; __syncthreads();
    for (int o = 64; o > 0; o >>= 1) { if (tid < o) red[tid] += red[tid+o]; __syncthreads(); }
    const float inv = 1.f / red[0];
    float* ap = g_att + ((long)bh * TSEQ + t) * TSEQ;
    for (int s = tid; s < TSEQ; s += 128) ap[s] = sc[s] * inv;
}

__global__ void proj_kernel()
{
    const int tok = blockIdx.x, tid = threadIdx.x;
    const float* dz = g_Dz + (long)tok * DIMIN;
    const float* xx = g_x  + (long)tok * DIMIN;
    float d1 = 0.f, d2 = 0.f;
    for (int i = tid; i < DIMIN; i += 256) { float a = dz[i]; d1 += a * xx[i]; d2 += a * a; }
    __shared__ float r1[256], r2[256];
    r1[tid] = d1; r2[tid] = d2; __syncthreads();
    for (int o = 128; o > 0; o >>= 1) { if (tid < o) { r1[tid] += r1[tid+o]; r2[tid] += r2[tid+o]; } __syncthreads(); }
    const float p = r1[0] / (r2[0] + 1e-6f);
    if (tid == 0) g_proj[tok] = p;
    for (int i = tid; i < DIMIN; i += 256)
        g_x2[(long)tok*DIMIN + i] = xx[i] - p * dz[i];
}

// ---------------- top-32: one warp per token ----------------
// Per-lane replace-min top-32 lists (strict > keeps lowest index on ties,
// matching jax top_k first-occurrence semantics), then 32-round warp merge.
#define TKW 4
__global__ void __launch_bounds__(128) topk_kernel()
{
    __shared__ float sv[TKW][32][33];
    __shared__ int   si[TKW][32][33];
    const int w = threadIdx.x >> 5, lane = threadIdx.x & 31;
    const int tok = blockIdx.x * TKW + w;
    const float* z = g_zin + (size_t)tok * WIDTH;
    float* V = sv[w][lane];
    int*   I = si[w][lane];

    float minv = 1e30f; int mins = 0;
    #pragma unroll
    for (int s = 0; s < 32; s++) {
        float v = z[s*32 + lane];
        V[s] = v; I[s] = s*32 + lane;
        if (v < minv) { minv = v; mins = s; }
    }
    for (int m = 32; m < 256; m += 4) {
        float v0 = z[(m+0)*32 + lane];
        float v1 = z[(m+1)*32 + lane];
        float v2 = z[(m+2)*32 + lane];
        float v3 = z[(m+3)*32 + lane];
        #pragma unroll
        for (int u = 0; u < 4; u++) {
            float v = (u==0)?v0:(u==1)?v1:(u==2)?v2:v3;
            if (v > minv) {               // strict: earlier index wins ties
                V[mins] = v; I[mins] = (m+u)*32 + lane;
                minv = 1e30f;
                #pragma unroll
                for (int s = 0; s < 32; s++) {
                    float x = V[s];
                    if (x < minv) { minv = x; mins = s; }
                }
            }
        }
    }
    __syncwarp();

    // merge: extract global top-32 by (value desc, index asc)
    for (int r = 0; r < 32; r++) {
        float bv = -1.f; int bi = 0x7FFFFFFF, bs = 0;
        #pragma unroll
        for (int s = 0; s < 32; s++) {
            float x = V[s]; int xi = I[s];
            if (x > bv || (x == bv && xi < bi)) { bv = x; bi = xi; bs = s; }
        }
        float wv = bv; int wi = bi;
        #pragma unroll
        for (int o = 16; o > 0; o >>= 1) {
            float ov = __shfl_xor_sync(0xFFFFFFFFu, wv, o);
            int   oi = __shfl_xor_sync(0xFFFFFFFFu, wi, o);
            if (ov > wv || (ov == wv && oi < wi)) { wv = ov; wi = oi; }
        }
        if (lane == 0) { g_tkv[tok*KVAL + r] = wv; g_tki[tok*KVAL + r] = wi; }
        if (bv == wv && bi == wi) V[bs] = -1.f;   // consume (indices unique per lane)
        __syncwarp();
    }
}

__global__ void final_kernel(const float* __restrict__ D, const float* __restrict__ b,
                             float* __restrict__ out)
{
    const int tok = blockIdx.x, tid = threadIdx.x;
    __shared__ float v[KVAL];
    __shared__ int   id[KVAL];
    if (tid < KVAL) { v[tid] = g_tkv[tok*KVAL + tid]; id[tid] = g_tki[tok*KVAL + tid]; }
    __syncthreads();
    const float p = g_proj[tok];
    for (int n = tid; n < DIMIN; n += 256) {
        float a = p * g_Dz[(long)tok*DIMIN + n] + b[n];
        #pragma unroll 8
        for (int j = 0; j < KVAL; j++)
            a += v[j] * D[(long)id[j]*DIMIN + n];
        out[(long)tok*DIMIN + n] = a;
    }
}

// ---------------- host launch ----------------
extern "C" void kernel_launch(void* const* d_in, const int* in_sizes, int n_in,
                              void* d_out, int out_size)
{
    const float* x_input = (const float*)d_in[0];
    const float* D       = (const float*)d_in[1];
    const float* b       = (const float*)d_in[2];
    const float* Wk      = (const float*)d_in[3];
    const float* bk      = (const float*)d_in[4];
    const float* Wq      = (const float*)d_in[5];
    const float* bq      = (const float*)d_in[6];
    const float* Wv      = (const float*)d_in[7];
    const float* bv      = (const float*)d_in[8];
    const float* Wo      = (const float*)d_in[9];
    const float* bo      = (const float*)d_in[10];
    float* out = (float*)d_out;

    void *px, *px2, *pzin, *pq, *pk, *pv, *pvt, *patt, *po, *pzp, *pdz, *pdt;
    cudaGetSymbolAddress(&px,    g_x);
    cudaGetSymbolAddress(&px2,   g_x2);
    cudaGetSymbolAddress(&pzin,  g_zin);
    cudaGetSymbolAddress(&pq,    g_q);
    cudaGetSymbolAddress(&pk,    g_k);
    cudaGetSymbolAddress(&pv,    g_v);
    cudaGetSymbolAddress(&pvt,   g_vT);
    cudaGetSymbolAddress(&patt,  g_att);
    cudaGetSymbolAddress(&po,    g_o);
    cudaGetSymbolAddress(&pzp,   g_zp);
    cudaGetSymbolAddress(&pdz,   g_Dz);
    cudaGetSymbolAddress(&pdt,   g_Dt);
    float* part = (float*)pvt;   // scratch for split-K partials (vT region reused)

    cudaFuncSetAttribute(tgemm<false,false>, cudaFuncAttributeMaxDynamicSharedMemorySize, TG_DSMEM);
    cudaFuncSetAttribute(tgemm<false,true >, cudaFuncAttributeMaxDynamicSharedMemorySize, TG_DSMEM);
    cudaFuncSetAttribute(tgemm<true ,false>, cudaFuncAttributeMaxDynamicSharedMemorySize, TG_DSMEM);
    cudaFuncSetAttribute(tgemm<true ,true >, cudaFuncAttributeMaxDynamicSharedMemorySize, TG_DSMEM);

    // 1) x = x_input - b ; D^T
    sub_b_kernel<<<(NTOK*DIMIN)/256, 256>>>(x_input, b);
    transpose_kernel<<<dim3(DIMIN/32, WIDTH/32), dim3(32,8)>>>(D);

    // 2) z_in = relu(lam * x @ D^T)   M=4096(MT=16) N=8192(NT=64) K=768
    tgemm<true,false><<<dim3(16*64,1,1), 256, TG_DSMEM>>>(
        (const float*)px, D, (float*)pzin, nullptr,
        DIMIN, DIMIN, WIDTH, 16, 64, LAM, 0, 0,0,0,0,1,
        nullptr, nullptr, nullptr, nullptr, 0);

    // 3) q/k split-K x4 into partials (y: q vs k(shift), z: K chunk)
    tgemm<false,false><<<dim3(16,2,4), 256, TG_DSMEM>>>(
        (const float*)pzin, Wq, part, nullptr,
        2048, WIDTH, NEMBDS, 16, 1, 1.0f, 0,
        2048, 2048, 0, QK_PART, 4,
        (const float*)pzin, Wk, part + 4*(size_t)QK_PART, nullptr, 1);
    reduce_qk_kernel<<<dim3(QK_PART/256, 2), 256>>>(part, bq, bk);

    // 4) v = shift(z_in) @ Wv^T + bv   M=4096 N=8192 K=8192
    tgemm<false,true><<<dim3(16*64,1,1), 256, TG_DSMEM>>>(
        (const float*)pzin, Wv, (float*)pv, bv,
        WIDTH, WIDTH, WIDTH, 16, 64, 1.0f, 1, 0,0,0,0,1,
        nullptr, nullptr, nullptr, nullptr, 0);

    // 5) causal softmax
    attn_softmax_kernel<<<dim3(TSEQ, NBATCH*NHEADS), 128>>>();

    // 6) v^T per batch
    transpose_v_kernel<<<dim3(WIDTH/32, TSEQ/32, NBATCH), dim3(32,8)>>>();

    // 7) o = a @ vT^T batched over 64 (b,h): M=512(MT=2) N=1024(NT=8) K=512
    tgemm<false,false><<<dim3(2*8,1,NBATCH*NHEADS), 256, TG_DSMEM>>>(
        (const float*)patt, (const float*)pvt, (float*)po, nullptr,
        TSEQ, TSEQ, WIDTH, 2, 8, 1.0f, 0,
        (long)TSEQ*TSEQ, (long)DHV*TSEQ, (long)TSEQ*WIDTH, (long)DHV, NHEADS,
        nullptr, nullptr, nullptr, nullptr, 0);

    // 8) z_pred_ = relu(o @ Wo^T + bo)
    tgemm<true,true><<<dim3(16*64,1,1), 256, TG_DSMEM>>>(
        (const float*)po, Wo, (float*)pzp, bo,
        WIDTH, WIDTH, WIDTH, 16, 64, 1.0f, 0, 0,0,0,0,1,
        nullptr, nullptr, nullptr, nullptr, 0);

    // 9) Dz = z_pred_ @ D  split-K x2 into partials  N=768(NT=6)
    tgemm<false,false><<<dim3(16*6,1,2), 256, TG_DSMEM>>>(
        (const float*)pzp, (const float*)pdt, part, nullptr,
        4096, WIDTH, DIMIN, 16, 6, 1.0f, 0,
        4096, 4096, 0, DZ_PART, 2,
        nullptr, nullptr, nullptr, nullptr, 0);
    reduce_dz_kernel<<<(NTOK*DIMIN)/256, 256>>>(part);

    // 10) proj + x2
    proj_kernel<<<NTOK, 256>>>();

    // 11) z_novel = relu(lam * x2 @ D^T)
    tgemm<true,false><<<dim3(16*64,1,1), 256, TG_DSMEM>>>(
        (const float*)px2, D, (float*)pzin, nullptr,
        DIMIN, DIMIN, WIDTH, 16, 64, LAM, 0, 0,0,0,0,1,
        nullptr, nullptr, nullptr, nullptr, 0);

    // 12) top-32 per token (1 warp/token)
    topk_kernel<<<NTOK/TKW, 128>>>();

    // 13) out = proj*Dz + b + sparse(z_novel)@D
    final_kernel<<<NTOK, 256>>>(D, b, out);
}

// round 14
// speedup vs baseline: 1.2618x; 1.2618x over previous
#include <cuda_runtime.h>
#include <cuda_bf16.h>
#include <cstdint>
#include <math.h>

// ---------------- problem constants ----------------
#define NTOK   4096      // B*T
#define TSEQ   512
#define NBATCH 8
#define DIMIN  768
#define WIDTH  8192
#define NHEADS 8
#define NEMBDS 128
#define DHQK   16
#define DHV    1024
#define KVAL   32
#define LAM    (1.0f/3072.0f)   // 1/(4*DIMIN)

#if defined(__CUDA_ARCH_FEAT_SM103_ALL) || defined(__CUDA_ARCH_FEAT_SM100_ALL) || defined(__CUDA_ARCH_SPECIFIC__)
#define TC_OK 1
#else
#define TC_OK 0
#endif

// ---------------- scratch (device globals; no allocation allowed) ----------------
__device__ float g_x   [NTOK*DIMIN];
__device__ float g_x2  [NTOK*DIMIN];
__device__ float g_zin [(size_t)NTOK*WIDTH];   // reused for z_novel
__device__ float g_q   [NTOK*NEMBDS];
__device__ float g_k   [NTOK*NEMBDS];
__device__ float g_v   [(size_t)NTOK*WIDTH];
__device__ float g_vT  [(size_t)NTOK*WIDTH];   // vT (step 6-7); also split-K partials (steps 3, 9)
__device__ float g_att [(size_t)NBATCH*NHEADS*TSEQ*TSEQ];
__device__ float g_o   [(size_t)NTOK*WIDTH];
__device__ float g_zp  [(size_t)NTOK*WIDTH];
__device__ float g_Dz  [NTOK*DIMIN];
__device__ float g_Dt  [DIMIN*WIDTH];          // D^T fp32 (for Dz GEMM)
__device__ float g_proj[NTOK];
__device__ float g_tkv [NTOK*KVAL];
__device__ int   g_tki [NTOK*KVAL];

#define QK_PART  524288          // 4096*128 elems per chunk
#define DZ_PART  3145728         // 4096*768 elems per chunk

// =====================================================================
// Shared helpers
// =====================================================================
#define GBK 64
#define PLANE_BYTES 16384           // 128 rows x 64 bf16 (128B/row, SW128)
#define STAGE_BYTES (6*PLANE_BYTES)
#define TG_DSMEM (2*STAGE_BYTES + 1024 + 64)

// cg2 kernel: stage = Ah,Al,Bh,Bl planes (64KB); double buffered
#define C2_STAGE (4*PLANE_BYTES)
#define C2_DSMEM (2*C2_STAGE + 1024 + 128)

__device__ __forceinline__ uint32_t smem_addr_u32(const void* p) {
    uint32_t a;
    asm("{ .reg .u64 t; cvta.to.shared.u64 t, %1; cvt.u32.u64 %0, t; }" : "=r"(a) : "l"(p));
    return a;
}
__device__ __forceinline__ uint32_t ctarank() {
    uint32_t r; asm("mov.u32 %0, %%cluster_ctarank;" : "=r"(r)); return r;
}

#if TC_OK
// SW128 K-major SMEM descriptor (version=1, layout=2, SBO=64, LBO=1)
__device__ __forceinline__ uint64_t mk_desc(uint32_t addr) {
    return ((uint64_t)2 << 61) | ((uint64_t)1 << 46) | ((uint64_t)64 << 32)
         | ((uint64_t)1 << 16) | ((uint64_t)((addr >> 4) & 0x3FFF));
}

__device__ __forceinline__ void mma_f16_ss(uint32_t d, uint64_t a, uint64_t b,
                                           uint32_t idesc, uint32_t en) {
    asm volatile(
        "{\n\t.reg .pred p;\n\tsetp.ne.u32 p, %4, 0;\n\t"
        "tcgen05.mma.cta_group::1.kind::f16 [%0], %1, %2, %3, {%5,%5,%5,%5}, p;\n\t}"
        :: "r"(d), "l"(a), "l"(b), "r"(idesc), "r"(en), "r"(0u) : "memory");
}

// cg2 variant: 8-entry disable-lane vector, mirrors test_2cta_mma_bf16.cu
__device__ __forceinline__ void mma_f16_ss_cg2(uint32_t d, uint64_t a, uint64_t b,
                                               uint32_t idesc, uint32_t en) {
    asm volatile(
        "{\n\t.reg .pred p;\n\tsetp.ne.u32 p, %6, 0;\n\t"
        "tcgen05.mma.cta_group::2.kind::f16 [%0], %1, %2, %3, "
        "{%4,%4,%4,%4,%4,%4,%4,%4}, p;\n\t}"
        :: "r"(d), "l"(a), "l"(b), "r"(idesc), "r"(0u), "r"(0u), "r"(en) : "memory");
}

#define MBAR_INIT(a, c) \
    asm volatile("mbarrier.init.shared.b64 [%0], %1;" :: "r"(a), "r"(c) : "memory")

#define MBAR_WAIT(mbar, par) do { \
    uint32_t _m = (mbar); uint32_t _p = (par); uint32_t _done; \
    asm volatile("{\n\t.reg .pred p;\n\t" \
        "mbarrier.try_wait.parity.acquire.cta.shared::cta.b64 p, [%1], %2;\n\t" \
        "selp.b32 %0, 1, 0, p;\n\t}" : "=r"(_done) : "r"(_m), "r"(_p) : "memory"); \
    if (!_done) { \
        asm volatile("{\n\t.reg .pred P1;\n\tWL_%=:\n\t" \
            "mbarrier.try_wait.parity.acquire.cta.shared::cta.b64 P1, [%0], %1, 0x989680;\n\t" \
            "@P1 bra.uni WD_%=;\n\tbra.uni WL_%=;\n\tWD_%=:\n\t}" \
            :: "r"(_m), "r"(_p) : "memory"); \
    } \
} while (0)

// bounded wait: gives up after ~4M polls (wrong answer instead of hang)
#define MBAR_WAIT_B(mbar, par) do { \
    uint32_t _m = (mbar); uint32_t _p = (par); uint32_t _ok = 0; \
    for (int _i = 0; _i < 4000000 && !_ok; _i++) { \
        asm volatile("{\n\t.reg .pred p;\n\t" \
            "mbarrier.try_wait.parity.acquire.cta.shared::cta.b64 p, [%1], %2;\n\t" \
            "selp.b32 %0, 1, 0, p;\n\t}" : "=r"(_ok) : "r"(_m), "r"(_p) : "memory"); \
    } \
} while (0)

#define MBAR_ARRIVE_RANK0(localaddr) \
    asm volatile("{\n\t.reg .b32 ra;\n\t" \
        "mapa.shared::cluster.u32 ra, %0, 0;\n\t" \
        "mbarrier.arrive.shared::cluster.b64 _, [ra];\n\t}" \
        :: "r"((uint32_t)(localaddr)) : "memory")

#define LDTM_X32(r, ta) \
    asm volatile("tcgen05.ld.sync.aligned.32x32b.x32.b32 " \
        "{%0,%1,%2,%3,%4,%5,%6,%7,%8,%9,%10,%11,%12,%13,%14,%15," \
        "%16,%17,%18,%19,%20,%21,%22,%23,%24,%25,%26,%27,%28,%29,%30,%31}, [%32];" \
        : "=r"((r)[0]),"=r"((r)[1]),"=r"((r)[2]),"=r"((r)[3]), \
          "=r"((r)[4]),"=r"((r)[5]),"=r"((r)[6]),"=r"((r)[7]), \
          "=r"((r)[8]),"=r"((r)[9]),"=r"((r)[10]),"=r"((r)[11]), \
          "=r"((r)[12]),"=r"((r)[13]),"=r"((r)[14]),"=r"((r)[15]), \
          "=r"((r)[16]),"=r"((r)[17]),"=r"((r)[18]),"=r"((r)[19]), \
          "=r"((r)[20]),"=r"((r)[21]),"=r"((r)[22]),"=r"((r)[23]), \
          "=r"((r)[24]),"=r"((r)[25]),"=r"((r)[26]),"=r"((r)[27]), \
          "=r"((r)[28]),"=r"((r)[29]),"=r"((r)[30]),"=r"((r)[31]) \
        : "r"(ta))

// load 128 rows x 64 k fp32, split hi/lo bf16, store SW128-swizzled.
__device__ __forceinline__ void ldsplit(const float* __restrict__ G, int ld, int rowbase,
                                        int kcol0, uint32_t sH, uint32_t sL, int shiftTok)
{
    const int tid = threadIdx.x;
    #pragma unroll
    for (int j = 0; j < 8; j++) {
        int idx = j*256 + tid;
        int row = idx >> 4, c4 = idx & 15;
        int gr = rowbase + row;
        float4 v;
        if (shiftTok && ((gr & (TSEQ-1)) == 0)) {
            v.x = 0.f; v.y = 0.f; v.z = 0.f; v.w = 0.f;
        } else {
            v = *(const float4*)(G + (size_t)(gr - shiftTok)*ld + kcol0 + c4*4);
        }
        __nv_bfloat162 h01 = __floats2bfloat162_rn(v.x, v.y);
        __nv_bfloat162 h23 = __floats2bfloat162_rn(v.z, v.w);
        float2 f01 = __bfloat1622float2(h01);
        float2 f23 = __bfloat1622float2(h23);
        __nv_bfloat162 l01 = __floats2bfloat162_rn(v.x - f01.x, v.y - f01.y);
        __nv_bfloat162 l23 = __floats2bfloat162_rn(v.z - f23.x, v.w - f23.y);
        uint32_t off = row*128 + c4*8;
        uint32_t sw  = off ^ ((off >> 3) & 0x70);   // SW128
        unsigned uh01 = *reinterpret_cast<unsigned*>(&h01);
        unsigned uh23 = *reinterpret_cast<unsigned*>(&h23);
        unsigned ul01 = *reinterpret_cast<unsigned*>(&l01);
        unsigned ul23 = *reinterpret_cast<unsigned*>(&l23);
        asm volatile("st.shared.v2.b32 [%0], {%1,%2};" :: "r"(sH + sw), "r"(uh01), "r"(uh23));
        asm volatile("st.shared.v2.b32 [%0], {%1,%2};" :: "r"(sL + sw), "r"(ul01), "r"(ul23));
    }
}

// cg2 B loader: plane row p -> global B row bn + (p>>6)*128 + rank*64 + (p&63)
__device__ __forceinline__ void ldsplitB2(const float* __restrict__ G, int ld, int bn,
                                          int rank, int kcol0, uint32_t sH, uint32_t sL)
{
    const int tid = threadIdx.x;
    #pragma unroll
    for (int j = 0; j < 8; j++) {
        int idx = j*256 + tid;
        int row = idx >> 4, c4 = idx & 15;
        int gr = bn + ((row >> 6) * 128) + rank*64 + (row & 63);
        float4 v = *(const float4*)(G + (size_t)gr*ld + kcol0 + c4*4);
        __nv_bfloat162 h01 = __floats2bfloat162_rn(v.x, v.y);
        __nv_bfloat162 h23 = __floats2bfloat162_rn(v.z, v.w);
        float2 f01 = __bfloat1622float2(h01);
        float2 f23 = __bfloat1622float2(h23);
        __nv_bfloat162 l01 = __floats2bfloat162_rn(v.x - f01.x, v.y - f01.y);
        __nv_bfloat162 l23 = __floats2bfloat162_rn(v.z - f23.x, v.w - f23.y);
        uint32_t off = row*128 + c4*8;
        uint32_t sw  = off ^ ((off >> 3) & 0x70);
        unsigned uh01 = *reinterpret_cast<unsigned*>(&h01);
        unsigned uh23 = *reinterpret_cast<unsigned*>(&h23);
        unsigned ul01 = *reinterpret_cast<unsigned*>(&l01);
        unsigned ul23 = *reinterpret_cast<unsigned*>(&l23);
        asm volatile("st.shared.v2.b32 [%0], {%1,%2};" :: "r"(sH + sw), "r"(uh01), "r"(uh23));
        asm volatile("st.shared.v2.b32 [%0], {%1,%2};" :: "r"(sL + sw), "r"(ul01), "r"(ul23));
    }
}
#endif  // TC_OK

// =====================================================================
// Single-CTA tcgen05 split-bf16 GEMM (proven R8/R10/R12 path), 256x128 tiles.
// =====================================================================
template<bool RELU, bool HASB>
__global__ void __launch_bounds__(256, 1) tgemm(
    const float* __restrict__ Ag, const float* __restrict__ Bg,
    float* __restrict__ Cg, const float* __restrict__ bias,
    int K, int ldab, int ldc, int MT, int NT, float alpha, int shiftA,
    long sA, long sB, long sC1, long sC2, int zdiv,
    const float* Ag2, const float* Bg2, float* Cg2, const float* bias2, int shiftA2)
{
    if (blockIdx.y == 1) { Ag = Ag2; Bg = Bg2; Cg = Cg2; bias = bias2; shiftA = shiftA2; }
    if (gridDim.z > 1) {
        int z = blockIdx.z;
        Ag += (long)z * sA;
        Bg += (long)z * sB;
        Cg += (long)(z / zdiv) * sC1 + (long)(z % zdiv) * sC2;
    }

    extern __shared__ char smem[];
    const int tid = threadIdx.x;

    int bid = blockIdx.x;
    const int GW = 8;
    int tpg = MT * GW;
    int g = bid / tpg, r = bid % tpg;
    int n0 = g * GW;
    int gw = NT - n0; if (gw > GW) gw = GW;
    const int bm = (r / gw) * 256;
    const int bn = (n0 + r % gw) * 128;

#if TC_OK
    uint32_t SB   = (smem_addr_u32(smem) + 1023u) & ~1023u;
    uint32_t ctrl = SB + 2*STAGE_BYTES;

    if (tid < 32) {
        asm volatile("tcgen05.alloc.cta_group::1.sync.aligned.shared::cta.b32 [%0], %1;"
                     :: "r"(ctrl), "r"(256u) : "memory");
        asm volatile("tcgen05.relinquish_alloc_permit.cta_group::1.sync.aligned;");
    }
    if (tid == 0) { MBAR_INIT(ctrl+16, 1); MBAR_INIT(ctrl+24, 1); }
    __syncthreads();
    uint32_t tmem;
    asm("ld.shared.b32 %0, [%1];" : "=r"(tmem) : "r"(ctrl));

    const uint32_t idesc = (1u<<4) | (1u<<7) | (1u<<10) | (16u<<17) | (8u<<24);
    const int KT = K / GBK;

    ldsplit(Ag, ldab, bm,       0, SB,                 SB +   PLANE_BYTES, shiftA);
    ldsplit(Ag, ldab, bm + 128, 0, SB + 2*PLANE_BYTES, SB + 3*PLANE_BYTES, shiftA);
    ldsplit(Bg, ldab, bn,       0, SB + 4*PLANE_BYTES, SB + 5*PLANE_BYTES, 0);
    __syncthreads();

    int ph0 = 0, ph1 = 0;
    for (int kt = 0; kt < KT; ++kt) {
        const int s = kt & 1;
        if (tid == 0) {
            asm volatile("fence.proxy.async.shared::cta;" ::: "memory");
            uint32_t base = SB + s*STAGE_BYTES;
            uint64_t dBh = mk_desc(base + 4*PLANE_BYTES);
            uint64_t dBl = mk_desc(base + 5*PLANE_BYTES);
            uint32_t en0 = (kt > 0) ? 1u : 0u;
            #pragma unroll
            for (int half = 0; half < 2; ++half) {
                uint64_t dAh = mk_desc(base + half*2*PLANE_BYTES);
                uint64_t dAl = mk_desc(base + half*2*PLANE_BYTES + PLANE_BYTES);
                uint32_t dcol = tmem + half*128;
                uint32_t eh = en0;
                #pragma unroll
                for (int st = 0; st < 4; ++st) {
                    uint64_t o = 2*st;
                    mma_f16_ss(dcol, dAh + o, dBh + o, idesc, eh); eh = 1u;
                    mma_f16_ss(dcol, dAh + o, dBl + o, idesc, 1u);
                    mma_f16_ss(dcol, dAl + o, dBh + o, idesc, 1u);
                }
            }
            asm volatile("tcgen05.commit.cta_group::1.mbarrier::arrive::one.shared::cluster.b64 [%0];"
                         :: "r"(ctrl + 16 + 8*s) : "memory");
            if (kt >= 1 && kt + 1 < KT) {
                int so = s ^ 1;
                if (so) { MBAR_WAIT(ctrl+24, ph1); ph1 ^= 1; }
                else    { MBAR_WAIT(ctrl+16, ph0); ph0 ^= 1; }
            }
        }
        __syncthreads();
        if (kt + 1 < KT) {
            uint32_t base = SB + (s^1)*STAGE_BYTES;
            int k0 = (kt+1)*GBK;
            ldsplit(Ag, ldab, bm,       k0, base,                 base +   PLANE_BYTES, shiftA);
            ldsplit(Ag, ldab, bm + 128, k0, base + 2*PLANE_BYTES, base + 3*PLANE_BYTES, shiftA);
            ldsplit(Bg, ldab, bn,       k0, base + 4*PLANE_BYTES, base + 5*PLANE_BYTES, 0);
        }
        __syncthreads();
    }
    if (tid == 0) {
        int sl = (KT-1) & 1;
        if (sl) { MBAR_WAIT(ctrl+24, ph1); }
        else    { MBAR_WAIT(ctrl+16, ph0); }
    }
    __syncthreads();
    asm volatile("tcgen05.fence::after_thread_sync;" ::: "memory");

    {
        const int wid = tid >> 5, lane = tid & 31;
        const int half = wid >> 2;
        const int row = bm + half*128 + (wid & 3)*32 + lane;
        #pragma unroll
        for (int cb = 0; cb < 128; cb += 32) {
            uint32_t rr[32];
            LDTM_X32(rr, tmem + half*128 + cb);
            asm volatile("tcgen05.wait::ld.sync.aligned;" ::: "memory");
            float* crow = Cg + (size_t)row*ldc + bn + cb;
            #pragma unroll
            for (int q4 = 0; q4 < 8; q4++) {
                float4 o4;
                float vv[4];
                #pragma unroll
                for (int t = 0; t < 4; t++) {
                    float v = alpha * __uint_as_float(rr[q4*4 + t]);
                    if (HASB) v += bias[bn + cb + q4*4 + t];
                    if (RELU) v = fmaxf(v, 0.f);
                    vv[t] = v;
                }
                o4.x = vv[0]; o4.y = vv[1]; o4.z = vv[2]; o4.w = vv[3];
                *(float4*)(crow + q4*4) = o4;
            }
        }
    }
    __syncthreads();
    if (tid < 32) {
        asm volatile("tcgen05.dealloc.cta_group::1.sync.aligned.b32 %0, %1;"
                     :: "r"(tmem), "r"(256u));
    }
#else
    (void)smem;
    for (int e = tid; e < 256*128; e += 256) {
        int i = e >> 7, j = e & 127;
        int gr = bm + i;
        bool zero = shiftA && ((gr & (TSEQ-1)) == 0);
        const float* arow = Ag + (size_t)(gr - shiftA)*ldab;
        const float* brow = Bg + (size_t)(bn + j)*ldab;
        float acc = 0.f;
        if (!zero)
            for (int k = 0; k < K; k++) acc += arow[k] * brow[k];
        float v = alpha * acc;
        if (HASB) v += bias[bn + j];
        if (RELU) v = fmaxf(v, 0.f);
        Cg[(size_t)gr*ldc + bn + j] = v;
    }
#endif
}

// =====================================================================
// cg2 pair GEMM: pair computes 256x256 tile; per CTA: A 128 rows + B 128 rows
// (halves of two N=128 sub-tiles). Encodings mirror test_2cta_mma_bf16.cu.
// =====================================================================
template<bool RELU, bool HASB>
__global__ void __launch_bounds__(256, 1) __cluster_dims__(2, 1, 1) tgemm2(
    const float* __restrict__ Ag, const float* __restrict__ Bg,
    float* __restrict__ Cg, const float* __restrict__ bias,
    int K, int ldab, int ldc, int MT, int NT, int shiftA)
{
    extern __shared__ char smem[];
    const int tid = threadIdx.x;
    const uint32_t rank = ctarank();

    const int pid = blockIdx.x >> 1;
    const int GW = 8;
    int tpg = MT * GW;
    int g = pid / tpg, r = pid % tpg;
    int n0 = g * GW;
    int gw = NT - n0; if (gw > GW) gw = GW;
    const int bm = (r / gw) * 256;
    const int bn = (n0 + r % gw) * 256;

#if TC_OK
    uint32_t SB   = (smem_addr_u32(smem) + 1023u) & ~1023u;
    uint32_t ctrl = SB + 2*C2_STAGE;
    // ctrl+0: tmem ptr; +16/+24: done[0/1] (count 1, multicast commit)
    // +32/+40: ready[0/1] (count 2, both CTAs arrive; leader waits)

    if (tid < 32) {
        asm volatile("tcgen05.alloc.cta_group::2.sync.aligned.shared::cta.b32 [%0], %1;"
                     :: "r"(ctrl), "r"(256u) : "memory");
    }
    if (tid == 0) {
        MBAR_INIT(ctrl+16, 1); MBAR_INIT(ctrl+24, 1);
        MBAR_INIT(ctrl+32, 2); MBAR_INIT(ctrl+40, 2);
    }
    __syncthreads();
    uint32_t tmem;
    asm("ld.shared.b32 %0, [%1];" : "=r"(tmem) : "r"(ctrl));

    // both CTAs' mbarriers must be live before any remote arrive / multicast
    asm volatile("barrier.cluster.arrive.aligned;" ::: "memory");
    asm volatile("barrier.cluster.wait.aligned;" ::: "memory");

    const uint32_t idesc = (1u<<4) | (1u<<7) | (1u<<10) | (16u<<17) | (16u<<24); // M=256, N=128
    const int KT = K / GBK;

    int phd0 = 0, phd1 = 0, phr0 = 0, phr1 = 0;
    for (int kt = 0; kt < KT; ++kt) {
        const int s = kt & 1;
        if (kt >= 2) {        // stage-free: MMA for this slot's previous use done
            if (tid == 0) {
                if (s) { MBAR_WAIT_B(ctrl+24, phd1); } else { MBAR_WAIT_B(ctrl+16, phd0); }
            }
            if (s) phd1 ^= 1; else phd0 ^= 1;
            __syncthreads();
        }
        uint32_t base = SB + s*C2_STAGE;
        int k0 = kt*GBK;
        ldsplit  (Ag, ldab, bm + rank*128, k0, base,                 base +   PLANE_BYTES, shiftA);
        ldsplitB2(Bg, ldab, bn, rank,      k0, base + 2*PLANE_BYTES, base + 3*PLANE_BYTES);
        __syncthreads();
        asm volatile("fence.proxy.async;" ::: "memory");
        if (tid == 0) MBAR_ARRIVE_RANK0(ctrl + 32 + 8*s);
        if (rank == 0 && tid == 0) {
            if (s) { MBAR_WAIT_B(ctrl+40, phr1); phr1 ^= 1; }
            else   { MBAR_WAIT_B(ctrl+32, phr0); phr0 ^= 1; }
            uint64_t dAh = mk_desc(base);
            uint64_t dAl = mk_desc(base + PLANE_BYTES);
            uint32_t en0 = (kt > 0) ? 1u : 0u;
            #pragma unroll
            for (int t = 0; t < 2; ++t) {
                uint64_t dBh = mk_desc(base + 2*PLANE_BYTES) + (uint64_t)t*512;
                uint64_t dBl = mk_desc(base + 3*PLANE_BYTES) + (uint64_t)t*512;
                uint32_t dcol = tmem + t*128;
                uint32_t eh = en0;
                #pragma unroll
                for (int st = 0; st < 4; ++st) {
                    uint64_t o = 2*st;
                    mma_f16_ss_cg2(dcol, dAh + o, dBh + o, idesc, eh); eh = 1u;
                    mma_f16_ss_cg2(dcol, dAh + o, dBl + o, idesc, 1u);
                    mma_f16_ss_cg2(dcol, dAl + o, dBh + o, idesc, 1u);
                }
            }
            asm volatile(
                "tcgen05.commit.cta_group::2.mbarrier::arrive::one.shared::cluster.multicast::cluster.b64 [%0], %1;"
                :: "r"(ctrl + 16 + 8*s), "h"((uint16_t)3) : "memory");
        }
    }
    {   // final: last commit implies all MMAs complete
        const int sl = (KT-1) & 1;
        if (tid == 0) {
            if (sl) { MBAR_WAIT_B(ctrl+24, phd1); } else { MBAR_WAIT_B(ctrl+16, phd0); }
        }
        __syncthreads();
    }
    asm volatile("tcgen05.fence::after_thread_sync;" ::: "memory");

    // epilogue: warps 0-3 read this CTA's M-half (128 rows) x 256 cols
    if (tid < 128) {
        const int wid = tid >> 5, lane = tid & 31;
        const int row = bm + rank*128 + wid*32 + lane;
        #pragma unroll
        for (int cb = 0; cb < 256; cb += 32) {
            uint32_t rr[32];
            LDTM_X32(rr, tmem + cb);
            asm volatile("tcgen05.wait::ld.sync.aligned;" ::: "memory");
            float* crow = Cg + (size_t)row*ldc + bn + cb;
            #pragma unroll
            for (int q4 = 0; q4 < 8; q4++) {
                float4 o4;
                float vv[4];
                #pragma unroll
                for (int t = 0; t < 4; t++) {
                    float v = __uint_as_float(rr[q4*4 + t]);
                    if (HASB) v += bias[bn + cb + q4*4 + t];
                    if (RELU) v = fmaxf(v, 0.f);
                    vv[t] = v;
                }
                o4.x = vv[0]; o4.y = vv[1]; o4.z = vv[2]; o4.w = vv[3];
                *(float4*)(crow + q4*4) = o4;
            }
        }
    }
    __syncthreads();
    if (tid < 32) {
        asm volatile("tcgen05.relinquish_alloc_permit.cta_group::2.sync.aligned;");
        asm volatile("tcgen05.dealloc.cta_group::2.sync.aligned.b32 %0, %1;"
                     :: "r"(tmem), "r"(256u));
    }
    asm volatile("barrier.cluster.arrive.aligned;" ::: "memory");
    asm volatile("barrier.cluster.wait.aligned;" ::: "memory");
#else
    (void)smem;
    for (int e = tid; e < 128*256; e += 256) {
        int i = e >> 8, j = e & 255;
        int gr = bm + (int)rank*128 + i;
        bool zero = shiftA && ((gr & (TSEQ-1)) == 0);
        const float* arow = Ag + (size_t)(gr - shiftA)*ldab;
        const float* brow = Bg + (size_t)(bn + j)*ldab;
        float acc = 0.f;
        if (!zero)
            for (int k = 0; k < K; k++) acc += arow[k] * brow[k];
        float v = acc;
        if (HASB) v += bias[bn + j];
        if (RELU) v = fmaxf(v, 0.f);
        Cg[(size_t)gr*ldc + bn + j] = v;
    }
#endif
}

// ---------------- split-K reduce kernels ----------------
__global__ void reduce_qk_kernel(const float* __restrict__ part,
                                 const float* __restrict__ bq, const float* __restrict__ bk)
{
    const int y = blockIdx.y;
    const int i = blockIdx.x * 256 + threadIdx.x;
    const float* p = part + (size_t)y * 4 * QK_PART;
    float s = p[i] + p[i + QK_PART] + p[i + 2*QK_PART] + p[i + 3*QK_PART];
    s += (y ? bk : bq)[i & (NEMBDS-1)];
    (y ? g_k : g_q)[i] = s;
}

__global__ void reduce_dz_kernel(const float* __restrict__ part)
{
    const int i = blockIdx.x * 256 + threadIdx.x;
    g_Dz[i] = part[i] + part[i + DZ_PART];
}

// ---------------- elementwise / glue kernels ----------------
__global__ void sub_b_kernel(const float* __restrict__ xin, const float* __restrict__ b)
{
    int i = blockIdx.x * 256 + threadIdx.x;
    g_x[i] = xin[i] - b[i % DIMIN];
}

__global__ void transpose_kernel(const float* __restrict__ D)
{
    __shared__ float t[32][33];
    int bx = blockIdx.x * 32;
    int by = blockIdx.y * 32;
    int x = threadIdx.x, y = threadIdx.y;
    #pragma unroll
    for (int i = 0; i < 32; i += 8)
        t[y+i][x] = D[(size_t)(by + y + i) * DIMIN + bx + x];
    __syncthreads();
    #pragma unroll
    for (int i = 0; i < 32; i += 8)
        g_Dt[(size_t)(bx + y + i) * WIDTH + by + x] = t[x][y+i];
}

__global__ void transpose_v_kernel()
{
    __shared__ float t[32][33];
    int bx = blockIdx.x * 32;
    int by = blockIdx.y * 32;
    int b  = blockIdx.z;
    int x = threadIdx.x, y = threadIdx.y;
    #pragma unroll
    for (int i = 0; i < 32; i += 8)
        t[y+i][x] = g_v[(size_t)(b*TSEQ + by + y + i) * WIDTH + bx + x];
    __syncthreads();
    #pragma unroll
    for (int i = 0; i < 32; i += 8)
        g_vT[(size_t)b*WIDTH*TSEQ + (size_t)(bx + y + i) * TSEQ + by + x] = t[x][y+i];
}

__global__ void attn_softmax_kernel()
{
    const int t  = blockIdx.x;
    const int bh = blockIdx.y;
    const int b  = bh >> 3, h = bh & 7;
    __shared__ float qs[DHQK];
    __shared__ float sc[TSEQ];
    __shared__ float red[128];
    const int tid = threadIdx.x;

    if (tid < DHQK) qs[tid] = g_q[(long)(b*TSEQ + t)*NEMBDS + h*DHQK + tid];
    __syncthreads();

    float lmax = -1e30f;
    for (int s = tid; s < TSEQ; s += 128) {
        float val = -1e30f;
        if (s <= t) {
            const float* kp = g_k + (long)(b*TSEQ + s)*NEMBDS + h*DHQK;
            float d = 0.f;
            #pragma unroll
            for (int i = 0; i < DHQK; i++) d += qs[i] * kp[i];
            val = d * 0.25f;
        }
        sc[s] = val;
        lmax = fmaxf(lmax, val);
    }
    red[tid] = lmax; __syncthreads();
    for (int o = 64; o > 0; o >>= 1) { if (tid < o) red[tid] = fmaxf(red[tid], red[tid+o]); __syncthreads(); }
    const float mx = red[0];
    __syncthreads();
    float lsum = 0.f;
    for (int s = tid; s < TSEQ; s += 128) {
        float e = (s <= t) ? expf(sc[s] - mx) : 0.f;
        sc[s] = e; lsum += e;
    }
    red[tid] = lsum; __syncthreads();
    for (int o = 64; o > 0; o >>= 1) { if (tid < o) red[tid] += red[tid+o]; __syncthreads(); }
    const float inv = 1.f / red[0];
    float* ap = g_att + ((long)bh * TSEQ + t) * TSEQ;
    for (int s = tid; s < TSEQ; s += 128) ap[s] = sc[s] * inv;
}

__global__ void proj_kernel()
{
    const int tok = blockIdx.x, tid = threadIdx.x;
    const float* dz = g_Dz + (long)tok * DIMIN;
    const float* xx = g_x  + (long)tok * DIMIN;
    float d1 = 0.f, d2 = 0.f;
    for (int i = tid; i < DIMIN; i += 256) { float a = dz[i]; d1 += a * xx[i]; d2 += a * a; }
    __shared__ float r1[256], r2[256];
    r1[tid] = d1; r2[tid] = d2; __syncthreads();
    for (int o = 128; o > 0; o >>= 1) { if (tid < o) { r1[tid] += r1[tid+o]; r2[tid] += r2[tid+o]; } __syncthreads(); }
    const float p = r1[0] / (r2[0] + 1e-6f);
    if (tid == 0) g_proj[tok] = p;
    for (int i = tid; i < DIMIN; i += 256)
        g_x2[(long)tok*DIMIN + i] = xx[i] - p * dz[i];
}

// ---------------- top-32: one warp per token ----------------
#define TKW 4
__global__ void __launch_bounds__(128) topk_kernel()
{
    __shared__ float sv[TKW][32][33];
    __shared__ int   si[TKW][32][33];
    const int w = threadIdx.x >> 5, lane = threadIdx.x & 31;
    const int tok = blockIdx.x * TKW + w;
    const float* z = g_zin + (size_t)tok * WIDTH;
    float* V = sv[w][lane];
    int*   I = si[w][lane];

    float minv = 1e30f; int mins = 0;
    #pragma unroll
    for (int s = 0; s < 32; s++) {
        float v = z[s*32 + lane];
        V[s] = v; I[s] = s*32 + lane;
        if (v < minv) { minv = v; mins = s; }
    }
    for (int m = 32; m < 256; m += 4) {
        float v0 = z[(m+0)*32 + lane];
        float v1 = z[(m+1)*32 + lane];
        float v2 = z[(m+2)*32 + lane];
        float v3 = z[(m+3)*32 + lane];
        #pragma unroll
        for (int u = 0; u < 4; u++) {
            float v = (u==0)?v0:(u==1)?v1:(u==2)?v2:v3;
            if (v > minv) {
                V[mins] = v; I[mins] = (m+u)*32 + lane;
                minv = 1e30f;
                #pragma unroll
                for (int s = 0; s < 32; s++) {
                    float x = V[s];
                    if (x < minv) { minv = x; mins = s; }
                }
            }
        }
    }
    __syncwarp();

    for (int r = 0; r < 32; r++) {
        float bv = -1.f; int bi = 0x7FFFFFFF, bs = 0;
        #pragma unroll
        for (int s = 0; s < 32; s++) {
            float x = V[s]; int xi = I[s];
            if (x > bv || (x == bv && xi < bi)) { bv = x; bi = xi; bs = s; }
        }
        float wv = bv; int wi = bi;
        #pragma unroll
        for (int o = 16; o > 0; o >>= 1) {
            float ov = __shfl_xor_sync(0xFFFFFFFFu, wv, o);
            int   oi = __shfl_xor_sync(0xFFFFFFFFu, wi, o);
            if (ov > wv || (ov == wv && oi < wi)) { wv = ov; wi = oi; }
        }
        if (lane == 0) { g_tkv[tok*KVAL + r] = wv; g_tki[tok*KVAL + r] = wi; }
        if (bv == wv && bi == wi) V[bs] = -1.f;
        __syncwarp();
    }
}

__global__ void final_kernel(const float* __restrict__ D, const float* __restrict__ b,
                             float* __restrict__ out)
{
    const int tok = blockIdx.x, tid = threadIdx.x;
    __shared__ float v[KVAL];
    __shared__ int   id[KVAL];
    if (tid < KVAL) { v[tid] = g_tkv[tok*KVAL + tid]; id[tid] = g_tki[tok*KVAL + tid]; }
    __syncthreads();
    const float p = g_proj[tok];
    for (int n = tid; n < DIMIN; n += 256) {
        float a = p * g_Dz[(long)tok*DIMIN + n] + b[n];
        #pragma unroll 8
        for (int j = 0; j < KVAL; j++)
            a += v[j] * D[(long)id[j]*DIMIN + n];
        out[(long)tok*DIMIN + n] = a;
    }
}

// ---------------- host launch ----------------
extern "C" void kernel_launch(void* const* d_in, const int* in_sizes, int n_in,
                              void* d_out, int out_size)
{
    const float* x_input = (const float*)d_in[0];
    const float* D       = (const float*)d_in[1];
    const float* b       = (const float*)d_in[2];
    const float* Wk      = (const float*)d_in[3];
    const float* bk      = (const float*)d_in[4];
    const float* Wq      = (const float*)d_in[5];
    const float* bq      = (const float*)d_in[6];
    const float* Wv      = (const float*)d_in[7];
    const float* bv      = (const float*)d_in[8];
    const float* Wo      = (const float*)d_in[9];
    const float* bo      = (const float*)d_in[10];
    float* out = (float*)d_out;

    void *px, *px2, *pzin, *pq, *pk, *pv, *pvt, *patt, *po, *pzp, *pdz, *pdt;
    cudaGetSymbolAddress(&px,    g_x);
    cudaGetSymbolAddress(&px2,   g_x2);
    cudaGetSymbolAddress(&pzin,  g_zin);
    cudaGetSymbolAddress(&pq,    g_q);
    cudaGetSymbolAddress(&pk,    g_k);
    cudaGetSymbolAddress(&pv,    g_v);
    cudaGetSymbolAddress(&pvt,   g_vT);
    cudaGetSymbolAddress(&patt,  g_att);
    cudaGetSymbolAddress(&po,    g_o);
    cudaGetSymbolAddress(&pzp,   g_zp);
    cudaGetSymbolAddress(&pdz,   g_Dz);
    cudaGetSymbolAddress(&pdt,   g_Dt);
    float* part = (float*)pvt;

    cudaFuncSetAttribute(tgemm<false,false>, cudaFuncAttributeMaxDynamicSharedMemorySize, TG_DSMEM);
    cudaFuncSetAttribute(tgemm<false,true >, cudaFuncAttributeMaxDynamicSharedMemorySize, TG_DSMEM);
    cudaFuncSetAttribute(tgemm<true ,false>, cudaFuncAttributeMaxDynamicSharedMemorySize, TG_DSMEM);
    cudaFuncSetAttribute(tgemm<true ,true >, cudaFuncAttributeMaxDynamicSharedMemorySize, TG_DSMEM);
    cudaFuncSetAttribute(tgemm2<false,true>, cudaFuncAttributeMaxDynamicSharedMemorySize, C2_DSMEM);
    cudaFuncSetAttribute(tgemm2<true ,true>, cudaFuncAttributeMaxDynamicSharedMemorySize, C2_DSMEM);

    // 1) x = x_input - b ; D^T
    sub_b_kernel<<<(NTOK*DIMIN)/256, 256>>>(x_input, b);
    transpose_kernel<<<dim3(DIMIN/32, WIDTH/32), dim3(32,8)>>>(D);

    // 2) z_in = relu(lam * x @ D^T)
    tgemm<true,false><<<dim3(16*64,1,1), 256, TG_DSMEM>>>(
        (const float*)px, D, (float*)pzin, nullptr,
        DIMIN, DIMIN, WIDTH, 16, 64, LAM, 0, 0,0,0,0,1,
        nullptr, nullptr, nullptr, nullptr, 0);

    // 3) q/k split-K x4
    tgemm<false,false><<<dim3(16,2,4), 256, TG_DSMEM>>>(
        (const float*)pzin, Wq, part, nullptr,
        2048, WIDTH, NEMBDS, 16, 1, 1.0f, 0,
        2048, 2048, 0, QK_PART, 4,
        (const float*)pzin, Wk, part + 4*(size_t)QK_PART, nullptr, 1);
    reduce_qk_kernel<<<dim3(QK_PART/256, 2), 256>>>(part, bq, bk);

    // 4) v = shift(z_in) @ Wv^T + bv  — cg2 256x256 pairs (512 pairs = 1024 CTAs)
    tgemm2<false,true><<<dim3(1024,1,1), 256, C2_DSMEM>>>(
        (const float*)pzin, Wv, (float*)pv, bv,
        WIDTH, WIDTH, WIDTH, 16, 32, 1);

    // 5) causal softmax
    attn_softmax_kernel<<<dim3(TSEQ, NBATCH*NHEADS), 128>>>();

    // 6) v^T per batch
    transpose_v_kernel<<<dim3(WIDTH/32, TSEQ/32, NBATCH), dim3(32,8)>>>();

    // 7) o = a @ vT^T batched over 64 (b,h)
    tgemm<false,false><<<dim3(2*8,1,NBATCH*NHEADS), 256, TG_DSMEM>>>(
        (const float*)patt, (const float*)pvt, (float*)po, nullptr,
        TSEQ, TSEQ, WIDTH, 2, 8, 1.0f, 0,
        (long)TSEQ*TSEQ, (long)DHV*TSEQ, (long)TSEQ*WIDTH, (long)DHV, NHEADS,
        nullptr, nullptr, nullptr, nullptr, 0);

    // 8) z_pred_ = relu(o @ Wo^T + bo) — cg2 256x256 pairs
    tgemm2<true,true><<<dim3(1024,1,1), 256, C2_DSMEM>>>(
        (const float*)po, Wo, (float*)pzp, bo,
        WIDTH, WIDTH, WIDTH, 16, 32, 0);

    // 9) Dz = z_pred_ @ D  split-K x2
    tgemm<false,false><<<dim3(16*6,1,2), 256, TG_DSMEM>>>(
        (const float*)pzp, (const float*)pdt, part, nullptr,
        4096, WIDTH, DIMIN, 16, 6, 1.0f, 0,
        4096, 4096, 0, DZ_PART, 2,
        nullptr, nullptr, nullptr, nullptr, 0);
    reduce_dz_kernel<<<(NTOK*DIMIN)/256, 256>>>(part);

    // 10) proj + x2
    proj_kernel<<<NTOK, 256>>>();

    // 11) z_novel = relu(lam * x2 @ D^T)
    tgemm<true,false><<<dim3(16*64,1,1), 256, TG_DSMEM>>>(
        (const float*)px2, D, (float*)pzin, nullptr,
        DIMIN, DIMIN, WIDTH, 16, 64, LAM, 0, 0,0,0,0,1,
        nullptr, nullptr, nullptr, nullptr, 0);

    // 12) top-32 per token
    topk_kernel<<<NTOK/TKW, 128>>>();

    // 13) out = proj*Dz + b + sparse(z_novel)@D
    final_kernel<<<NTOK, 256>>>(D, b, out);
}